// round 14
// baseline (speedup 1.0000x reference)
#include <cuda_runtime.h>
#include <cuda_bf16.h>
#include <cstdint>

static constexpr int B_ = 8;
static constexpr int C_ = 128;
static constexpr int N_ = 3136;                 // 56*56
static constexpr int NT = 25;                   // ceil(N/128)
static constexpr size_t NN = (size_t)N_ * N_;
static constexpr size_t XE = (size_t)B_ * C_ * N_;

__device__ __nv_bfloat16 g_P_hi[(size_t)B_ * NN];        // exp(E) split hi
__device__ __nv_bfloat16 g_P_lo[(size_t)B_ * NN];        // exp(E) split lo
__device__ __nv_bfloat16 g_xT_hi[(size_t)B_ * N_ * C_];  // x^T split hi  [b][n][c]
__device__ __nv_bfloat16 g_xT_lo[(size_t)B_ * N_ * C_];  // x^T split lo
__device__ __nv_bfloat16 g_V_hi[XE];                     // (x * inv) split hi [b][c][i]
__device__ __nv_bfloat16 g_V_lo[XE];
__device__ float         g_psum[(size_t)B_ * NT * N_];   // partial row sums of P

// ---------------------------------------------------------------------------
// helpers
// ---------------------------------------------------------------------------
__device__ __forceinline__ uint32_t smem_u32(const void* p) {
    uint32_t a;
    asm("{ .reg .u64 t; cvta.to.shared.u64 t, %1; cvt.u32.u64 %0, t; }" : "=r"(a) : "l"(p));
    return a;
}
__device__ __forceinline__ void ldm_x4(uint32_t* r, uint32_t a) {
    asm volatile("ldmatrix.sync.aligned.m8n8.x4.shared.b16 {%0,%1,%2,%3}, [%4];"
                 : "=r"(r[0]), "=r"(r[1]), "=r"(r[2]), "=r"(r[3]) : "r"(a));
}
__device__ __forceinline__ void mma_bf16(float* d, const uint32_t* a, const uint32_t* b) {
    asm volatile("mma.sync.aligned.m16n8k16.row.col.f32.bf16.bf16.f32 "
                 "{%0,%1,%2,%3}, {%4,%5,%6,%7}, {%8,%9}, {%0,%1,%2,%3};"
                 : "+f"(d[0]), "+f"(d[1]), "+f"(d[2]), "+f"(d[3])
                 : "r"(a[0]), "r"(a[1]), "r"(a[2]), "r"(a[3]), "r"(b[0]), "r"(b[1]));
}
__device__ __forceinline__ void split_bf16(float v, __nv_bfloat16& h, __nv_bfloat16& l) {
    h = __float2bfloat16(v);
    l = __float2bfloat16(v - __bfloat162float(h));
}

static constexpr int PITCHB = 80;               // 32 bf16 k-chunk rows, pitch 40 bf16
static constexpr int TILEB = 128 * PITCHB;      // 10240
static constexpr int SA_H = 0, SA_L = 10240, SB_H = 20480, SB_L = 30720;
static constexpr int BUFB = 40960;
static constexpr int K1_SMEM = 2 * BUFB;        // fp32 stage reuses buffers post-loop

// k3: V 128x32 hi/lo + P 64x32 hi/lo per buffer, 2-stage ring, 1 sync/chunk
static constexpr int PTILEB = 64 * PITCHB;                  // 5120
static constexpr int K3_SBH = 2 * TILEB;                    // 20480
static constexpr int K3_SBL = K3_SBH + PTILEB;              // 25600
static constexpr int K3_BUF = K3_SBL + PTILEB;              // 30720
static constexpr int K3_SMEM = 2 * K3_BUF;                  // 61440 -> 3 CTAs/SM

// ---------------------------------------------------------------------------
// K0: split/transpose x -> xT_hi/lo [b][n][c]
// ---------------------------------------------------------------------------
__global__ void k0_split(const float* __restrict__ x) {
    __shared__ float t[32][33];
    const int b = blockIdx.z, c0 = blockIdx.x * 32, n0 = blockIdx.y * 32;
    const int tx = threadIdx.x, ty = threadIdx.y;   // 32 x 8
    const float* xb = x + (size_t)b * C_ * N_;
    #pragma unroll
    for (int r = 0; r < 4; r++) {
        int c = ty + r * 8;
        t[c][tx] = xb[(size_t)(c0 + c) * N_ + n0 + tx];
    }
    __syncthreads();
    __nv_bfloat16* Th = g_xT_hi + (size_t)b * N_ * C_;
    __nv_bfloat16* Tl = g_xT_lo + (size_t)b * N_ * C_;
    #pragma unroll
    for (int r = 0; r < 4; r++) {
        int n = ty + r * 8;
        float v = t[tx][n];
        __nv_bfloat16 h, l;
        split_bf16(v, h, l);
        size_t o = (size_t)(n0 + n) * C_ + c0 + tx;
        Th[o] = h; Tl[o] = l;
    }
}

// ---------------------------------------------------------------------------
// K1: P-tile = exp(mask(xT * xT^T)), symmetry tj>=ti (early exit grid),
// cp.async double buffer. grid (25, 25, B), 256 threads (8 warps 2m x 4n).
// ---------------------------------------------------------------------------
__device__ __forceinline__ void k1_mma_chunk(float acc[4][4][4], uint32_t base,
                                             int a_off, int b_off0, int b_off1) {
    #pragma unroll
    for (int ks = 0; ks < 2; ks++) {
        const int kb = ks * 32;
        uint32_t ah[4][4], al[4][4], bh[2][4], bl[2][4];
        #pragma unroll
        for (int ma = 0; ma < 4; ma++)
            ldm_x4(ah[ma], base + SA_H + a_off + ma * 16 * PITCHB + kb);
        ldm_x4(bh[0], base + SB_H + b_off0 + kb);
        ldm_x4(bh[1], base + SB_H + b_off1 + kb);
        #pragma unroll
        for (int ma = 0; ma < 4; ma++)
            #pragma unroll
            for (int na = 0; na < 4; na++)
                mma_bf16(acc[ma][na], ah[ma], &bh[na >> 1][(na & 1) * 2]);
        ldm_x4(bl[0], base + SB_L + b_off0 + kb);
        ldm_x4(bl[1], base + SB_L + b_off1 + kb);
        #pragma unroll
        for (int ma = 0; ma < 4; ma++)
            #pragma unroll
            for (int na = 0; na < 4; na++)
                mma_bf16(acc[ma][na], ah[ma], &bl[na >> 1][(na & 1) * 2]);
        #pragma unroll
        for (int ma = 0; ma < 4; ma++)
            ldm_x4(al[ma], base + SA_L + a_off + ma * 16 * PITCHB + kb);
        #pragma unroll
        for (int ma = 0; ma < 4; ma++)
            #pragma unroll
            for (int na = 0; na < 4; na++)
                mma_bf16(acc[ma][na], al[ma], &bh[na >> 1][(na & 1) * 2]);
    }
}

__device__ __forceinline__ void k1_issue(uint32_t sbuf, int tid, int c0, int i0, int j0,
                                         const __nv_bfloat16* Xh, const __nv_bfloat16* Xl) {
    #pragma unroll
    for (int q = 0; q < 8; q++) {
        int e = tid + q * 256;
        int tile = e >> 9, row = (e >> 2) & 127, p = e & 3;
        int gr = min(((tile < 2) ? i0 : j0) + row, N_ - 1);
        const __nv_bfloat16* src = ((tile & 1) ? Xl : Xh) + (size_t)gr * C_ + c0;
        uint32_t dst = sbuf + tile * TILEB + row * PITCHB + p * 16;
        asm volatile("cp.async.cg.shared.global [%0], [%1], 16;"
                     :: "r"(dst), "l"((const char*)src + p * 16) : "memory");
    }
    asm volatile("cp.async.commit_group;" ::: "memory");
}

__global__ void __launch_bounds__(256, 2) k1_gram() {
    extern __shared__ char smem[];
    const uint32_t sb = smem_u32(smem);
    const int tid = threadIdx.x, wid = tid >> 5, lane = tid & 31;
    const int g = lane >> 2, t4 = lane & 3;
    const int ti = blockIdx.x, tj = blockIdx.y, b = blockIdx.z;
    if (tj < ti) return;
    const int i0 = ti * 128, j0 = tj * 128;
    const int wm = wid & 1, wn = wid >> 1;

    const int ab = lane >> 3;
    const int a_row = (ab & 1) * 8 + (lane & 7);
    const int a_colb = ((ab >> 1) * 8) * 2;
    const int a_off = (wm * 64 + a_row) * PITCHB + a_colb;
    const int b_row4 = lane & 7;
    const int b_k8 = ((lane >> 3) & 1) * 16;
    const int b_nsel = lane >> 4;
    const int b_off0 = (wn * 32 + (0 * 2 + b_nsel) * 8 + b_row4) * PITCHB + b_k8;
    const int b_off1 = (wn * 32 + (1 * 2 + b_nsel) * 8 + b_row4) * PITCHB + b_k8;

    const __nv_bfloat16* Xh = g_xT_hi + (size_t)b * N_ * C_;
    const __nv_bfloat16* Xl = g_xT_lo + (size_t)b * N_ * C_;

    float acc[4][4][4];
    #pragma unroll
    for (int i = 0; i < 4; i++)
        #pragma unroll
        for (int j = 0; j < 4; j++)
            #pragma unroll
            for (int q = 0; q < 4; q++) acc[i][j][q] = 0.0f;

    k1_issue(sb, tid, 0, i0, j0, Xh, Xl);
    #pragma unroll
    for (int kc = 0; kc < 4; kc++) {
        if (kc < 3) {
            k1_issue(sb + ((kc + 1) & 1) * BUFB, tid, (kc + 1) * 32, i0, j0, Xh, Xl);
            asm volatile("cp.async.wait_group 1;" ::: "memory");
        } else {
            asm volatile("cp.async.wait_group 0;" ::: "memory");
        }
        __syncthreads();
        k1_mma_chunk(acc, sb + (kc & 1) * BUFB, a_off, b_off0, b_off1);
        __syncthreads();
    }

    // stage exp(masked E) fp32, pitch 133 (reuses buffer smem)
    float* stg = (float*)smem;
    const bool diagblk = (ti == tj);
    #pragma unroll
    for (int ma = 0; ma < 4; ma++)
        #pragma unroll
        for (int na = 0; na < 4; na++) {
            int r0 = wm * 64 + ma * 16 + g;
            int cc = wn * 32 + na * 8 + t4 * 2;
            float d0 = acc[ma][na][0], d1 = acc[ma][na][1];
            float d2 = acc[ma][na][2], d3 = acc[ma][na][3];
            if (diagblk) {
                if (r0 == cc) d0 = 0.0f;
                if (r0 == cc + 1) d1 = 0.0f;
                if (r0 + 8 == cc) d2 = 0.0f;
                if (r0 + 8 == cc + 1) d3 = 0.0f;
            }
            stg[r0 * 133 + cc] = __expf(d0);
            stg[r0 * 133 + cc + 1] = __expf(d1);
            stg[(r0 + 8) * 133 + cc] = __expf(d2);
            stg[(r0 + 8) * 133 + cc + 1] = __expf(d3);
        }
    __syncthreads();

    const int ilim = min(128, N_ - i0), jlim = min(128, N_ - j0);

    if (tid < 128) {                      // row sums, split chains
        int row = tid;
        if (row < ilim) {
            float s0 = 0.0f, s1 = 0.0f, s2 = 0.0f, s3 = 0.0f;
            const float* r = stg + row * 133;
            int c = 0;
            for (; c + 3 < jlim; c += 4) {
                s0 += r[c]; s1 += r[c + 1]; s2 += r[c + 2]; s3 += r[c + 3];
            }
            for (; c < jlim; c++) s0 += r[c];
            g_psum[((size_t)b * NT + tj) * N_ + i0 + row] = (s0 + s1) + (s2 + s3);
        }
    } else if (ti != tj) {                // col sums (mirror), split chains
        int jr = tid - 128;
        if (jr < jlim) {
            float s0 = 0.0f, s1 = 0.0f, s2 = 0.0f, s3 = 0.0f;
            const float* cptr = stg + jr;
            int ic = 0;
            for (; ic + 3 < ilim; ic += 4) {
                s0 += cptr[ic * 133];
                s1 += cptr[(ic + 1) * 133];
                s2 += cptr[(ic + 2) * 133];
                s3 += cptr[(ic + 3) * 133];
            }
            for (; ic < ilim; ic++) s0 += cptr[ic * 133];
            g_psum[((size_t)b * NT + ti) * N_ + j0 + jr] = (s0 + s1) + (s2 + s3);
        }
    }

    __nv_bfloat162* Ph = (__nv_bfloat162*)(g_P_hi + (size_t)b * NN);
    __nv_bfloat162* Pl = (__nv_bfloat162*)(g_P_lo + (size_t)b * NN);
    for (int e = tid; e < 8192; e += 256) {
        int r = e >> 6, cp2 = e & 63;
        if (r < ilim && 2 * cp2 < jlim) {
            float a0 = stg[r * 133 + 2 * cp2], a1 = stg[r * 133 + 2 * cp2 + 1];
            __nv_bfloat16 h0, l0, h1, l1;
            split_bf16(a0, h0, l0);
            split_bf16(a1, h1, l1);
            size_t pi = ((size_t)(i0 + r) * N_ + j0) / 2 + cp2;
            Ph[pi] = __halves2bfloat162(h0, h1);
            Pl[pi] = __halves2bfloat162(l0, l1);
        }
    }
    if (ti != tj) {
        for (int e = tid; e < 8192; e += 256) {
            int jr = e >> 6, icp = e & 63;
            if (jr < jlim && 2 * icp < ilim) {
                float a0 = stg[(2 * icp) * 133 + jr], a1 = stg[(2 * icp + 1) * 133 + jr];
                __nv_bfloat16 h0, l0, h1, l1;
                split_bf16(a0, h0, l0);
                split_bf16(a1, h1, l1);
                size_t pi = ((size_t)(j0 + jr) * N_ + i0) / 2 + icp;
                Ph[pi] = __halves2bfloat162(h0, h1);
                Pl[pi] = __halves2bfloat162(l0, l1);
            }
        }
    }
}

// ---------------------------------------------------------------------------
// K2b: per-block inv for a 32-i slice, then Vs split. grid (98, B), 256 thr.
// ---------------------------------------------------------------------------
__global__ void __launch_bounds__(256) k2b_vscale(const float* __restrict__ x,
                                                  const float* __restrict__ gamma_p,
                                                  float* __restrict__ g_sec) {
    const int b = blockIdx.y, i0 = blockIdx.x * 32;
    const int tid = threadIdx.x;
    __shared__ float sinv[32];
    if (tid < 32) {
        const float* p = g_psum + (size_t)b * NT * N_ + i0 + tid;
        float s = 0.0f;
        #pragma unroll
        for (int t = 0; t < NT; t++) s += p[(size_t)t * N_];
        sinv[tid] = 1.0f / s;
    }
    if (b == 0 && blockIdx.x == 0 && tid == 0) g_sec[0] = gamma_p[0];
    __syncthreads();

    const int c = tid >> 1, ih = (tid & 1) * 16;
    const float* src = x + ((size_t)b * C_ + c) * N_ + i0 + ih;
    const size_t dsto = ((size_t)b * C_ + c) * N_ + i0 + ih;
    #pragma unroll
    for (int q = 0; q < 16; q += 2) {
        float2 f = *(const float2*)(src + q);
        float a0 = f.x * sinv[ih + q];
        float a1 = f.y * sinv[ih + q + 1];
        __nv_bfloat16 h0, l0, h1, l1;
        split_bf16(a0, h0, l0);
        split_bf16(a1, h1, l1);
        *(__nv_bfloat162*)(g_V_hi + dsto + q) = __halves2bfloat162(h0, h1);
        *(__nv_bfloat162*)(g_V_lo + dsto + q) = __halves2bfloat162(l0, l1);
    }
}

// ---------------------------------------------------------------------------
// K3: out[c,j] = sum_i Vs[c,i] * P[j,i]. Tile 128c x 64j, grid 392, 2-stage
// ring with wait->sync->issue->mma (1 sync/chunk, race-free), 3 CTAs/SM.
// 8 warps as 4m x 2n. Fused relu/gamma/residual + x passthrough epilogue.
// ---------------------------------------------------------------------------
__device__ __forceinline__ void k3_issue(uint32_t sbuf, int tid, int iC, int j0,
                                         const __nv_bfloat16* Vh, const __nv_bfloat16* Vl,
                                         const __nv_bfloat16* Ph, const __nv_bfloat16* Pl) {
    #pragma unroll
    for (int q = 0; q < 6; q++) {
        int e = tid + q * 256;             // e in [0, 1536)
        int p = e & 3;
        uint32_t dst;
        const __nv_bfloat16* src;
        if (e < 1024) {                    // V tiles: 128 rows
            int row = (e >> 2) & 127;
            int hl = e >> 9;
            dst = sbuf + hl * TILEB + row * PITCHB + p * 16;
            src = (hl ? Vl : Vh) + (size_t)row * N_ + iC;
        } else {                           // P tiles: 64 rows
            int e2 = e - 1024;
            int row = (e2 >> 2) & 63;
            int hl = e2 >> 8;
            dst = sbuf + (hl ? K3_SBL : K3_SBH) + row * PITCHB + p * 16;
            src = (hl ? Pl : Ph) + (size_t)(j0 + row) * N_ + iC;
        }
        asm volatile("cp.async.cg.shared.global [%0], [%1], 16;"
                     :: "r"(dst), "l"((const char*)src + p * 16) : "memory");
    }
    asm volatile("cp.async.commit_group;" ::: "memory");
}

__device__ __forceinline__ void k3_mma_chunk(float acc[2][4][4], uint32_t base,
                                             int a_off, int b_off0, int b_off1) {
    #pragma unroll
    for (int ks = 0; ks < 2; ks++) {
        const int kb = ks * 32;
        uint32_t ah[2][4], al[2][4], bh[2][4], bl[2][4];
        #pragma unroll
        for (int ma = 0; ma < 2; ma++)
            ldm_x4(ah[ma], base + SA_H + a_off + ma * 16 * PITCHB + kb);
        ldm_x4(bh[0], base + K3_SBH + b_off0 + kb);
        ldm_x4(bh[1], base + K3_SBH + b_off1 + kb);
        #pragma unroll
        for (int ma = 0; ma < 2; ma++)
            #pragma unroll
            for (int na = 0; na < 4; na++)
                mma_bf16(acc[ma][na], ah[ma], &bh[na >> 1][(na & 1) * 2]);
        ldm_x4(bl[0], base + K3_SBL + b_off0 + kb);
        ldm_x4(bl[1], base + K3_SBL + b_off1 + kb);
        #pragma unroll
        for (int ma = 0; ma < 2; ma++)
            #pragma unroll
            for (int na = 0; na < 4; na++)
                mma_bf16(acc[ma][na], ah[ma], &bl[na >> 1][(na & 1) * 2]);
        #pragma unroll
        for (int ma = 0; ma < 2; ma++)
            ldm_x4(al[ma], base + SA_L + a_off + ma * 16 * PITCHB + kb);
        #pragma unroll
        for (int ma = 0; ma < 2; ma++)
            #pragma unroll
            for (int na = 0; na < 4; na++)
                mma_bf16(acc[ma][na], al[ma], &bh[na >> 1][(na & 1) * 2]);
    }
}

__global__ void __launch_bounds__(256, 3) k3_out(const float* __restrict__ x,
                                                 const float* __restrict__ gamma_p,
                                                 float* __restrict__ y_out,
                                                 float* __restrict__ o_out,
                                                 float* __restrict__ x_out) {
    extern __shared__ char smem[];
    const uint32_t sb = smem_u32(smem);
    const int tid = threadIdx.x, wid = tid >> 5, lane = tid & 31;
    const int g = lane >> 2, t4 = lane & 3;
    const int b = blockIdx.x % B_, j0 = (blockIdx.x / B_) * 64;
    const int wm = wid & 3, wn = wid >> 2;      // 4m x 2n

    const int ab = lane >> 3;
    const int a_row = (ab & 1) * 8 + (lane & 7);
    const int a_colb = ((ab >> 1) * 8) * 2;
    const int a_off = (wm * 32 + a_row) * PITCHB + a_colb;
    const int b_row4 = lane & 7;
    const int b_k8 = ((lane >> 3) & 1) * 16;
    const int b_nsel = lane >> 4;
    const int b_off0 = (wn * 32 + (0 * 2 + b_nsel) * 8 + b_row4) * PITCHB + b_k8;
    const int b_off1 = (wn * 32 + (1 * 2 + b_nsel) * 8 + b_row4) * PITCHB + b_k8;

    const __nv_bfloat16* Vh = g_V_hi + (size_t)b * C_ * N_;
    const __nv_bfloat16* Vl = g_V_lo + (size_t)b * C_ * N_;
    const __nv_bfloat16* Ph = g_P_hi + (size_t)b * NN;
    const __nv_bfloat16* Pl = g_P_lo + (size_t)b * NN;
    const float* xb = x + (size_t)b * C_ * N_;

    float acc[2][4][4];
    #pragma unroll
    for (int i = 0; i < 2; i++)
        #pragma unroll
        for (int j = 0; j < 4; j++)
            #pragma unroll
            for (int q = 0; q < 4; q++) acc[i][j][q] = 0.0f;

    k3_issue(sb, tid, 0, j0, Vh, Vl, Ph, Pl);

    for (int kc = 0; kc < 98; kc++) {
        asm volatile("cp.async.wait_group 0;" ::: "memory");
        __syncthreads();                    // all warps done with mma(kc-1)
        if (kc < 97)
            k3_issue(sb + ((kc + 1) & 1) * K3_BUF, tid, (kc + 1) * 32, j0, Vh, Vl, Ph, Pl);
        k3_mma_chunk(acc, sb + (kc & 1) * K3_BUF, a_off, b_off0, b_off1);
    }

    const float gamma = *gamma_p;
    #pragma unroll
    for (int ma = 0; ma < 2; ma++)
        #pragma unroll
        for (int na = 0; na < 4; na++) {
            int c = wm * 32 + ma * 16 + g;
            int j = j0 + wn * 32 + na * 8 + t4 * 2;
            size_t idx0 = ((size_t)b * C_ + c) * N_ + j;
            size_t idx1 = ((size_t)b * C_ + c + 8) * N_ + j;
            float o0 = fmaxf(acc[ma][na][0], 0.0f);
            float o1 = fmaxf(acc[ma][na][1], 0.0f);
            float o2 = fmaxf(acc[ma][na][2], 0.0f);
            float o3 = fmaxf(acc[ma][na][3], 0.0f);
            float2 xi0 = *(const float2*)&xb[(size_t)c * N_ + j];
            float2 xi1 = *(const float2*)&xb[(size_t)(c + 8) * N_ + j];
            *(float2*)&o_out[idx0] = make_float2(o0, o1);
            *(float2*)&o_out[idx1] = make_float2(o2, o3);
            *(float2*)&y_out[idx0] = make_float2(gamma * o0 + xi0.x, gamma * o1 + xi0.y);
            *(float2*)&y_out[idx1] = make_float2(gamma * o2 + xi1.x, gamma * o3 + xi1.y);
            *(float2*)&x_out[idx0] = xi0;
            *(float2*)&x_out[idx1] = xi1;
        }
}

// ---------------------------------------------------------------------------
extern "C" void kernel_launch(void* const* d_in, const int* in_sizes, int n_in,
                              void* d_out, int out_size) {
    const float* x     = (const float*)d_in[0];
    const float* gamma = (const float*)d_in[1];
    float* out = (float*)d_out;

    float* y_sec = out;
    float* o_sec = out + XE;
    float* x_sec = out + 2 * XE;
    float* g_sec = out + 3 * XE;

    cudaFuncSetAttribute(k1_gram, cudaFuncAttributeMaxDynamicSharedMemorySize, K1_SMEM);
    cudaFuncSetAttribute(k3_out, cudaFuncAttributeMaxDynamicSharedMemorySize, K3_SMEM);

    k0_split<<<dim3(4, 98, B_), dim3(32, 8)>>>(x);
    k1_gram<<<dim3(NT, NT, B_), 256, K1_SMEM>>>();
    k2b_vscale<<<dim3(98, B_), 256>>>(x, gamma, g_sec);
    k3_out<<<dim3(49 * B_), 256, K3_SMEM>>>(x, gamma, y_sec, o_sec, x_sec);
}

// round 15
// speedup vs baseline: 1.1111x; 1.1111x over previous
#include <cuda_runtime.h>
#include <cuda_bf16.h>
#include <cstdint>

static constexpr int B_ = 8;
static constexpr int C_ = 128;
static constexpr int N_ = 3136;                 // 56*56
static constexpr int NT = 25;                   // ceil(N/128)
static constexpr size_t NN = (size_t)N_ * N_;
static constexpr size_t XE = (size_t)B_ * C_ * N_;

__device__ __nv_bfloat16 g_P_hi[(size_t)B_ * NN];        // exp(E) split hi
__device__ __nv_bfloat16 g_P_lo[(size_t)B_ * NN];        // exp(E) split lo
__device__ __nv_bfloat16 g_xT_hi[(size_t)B_ * N_ * C_];  // x^T split hi  [b][n][c]
__device__ __nv_bfloat16 g_xT_lo[(size_t)B_ * N_ * C_];  // x^T split lo
__device__ __nv_bfloat16 g_V_hi[XE];                     // (x * inv) split hi [b][c][i]
__device__ __nv_bfloat16 g_V_lo[XE];
__device__ float         g_psum[(size_t)B_ * NT * N_];   // partial row sums of P

// ---------------------------------------------------------------------------
// helpers
// ---------------------------------------------------------------------------
__device__ __forceinline__ uint32_t smem_u32(const void* p) {
    uint32_t a;
    asm("{ .reg .u64 t; cvta.to.shared.u64 t, %1; cvt.u32.u64 %0, t; }" : "=r"(a) : "l"(p));
    return a;
}
__device__ __forceinline__ void ldm_x4(uint32_t* r, uint32_t a) {
    asm volatile("ldmatrix.sync.aligned.m8n8.x4.shared.b16 {%0,%1,%2,%3}, [%4];"
                 : "=r"(r[0]), "=r"(r[1]), "=r"(r[2]), "=r"(r[3]) : "r"(a));
}
__device__ __forceinline__ void mma_bf16(float* d, const uint32_t* a, const uint32_t* b) {
    asm volatile("mma.sync.aligned.m16n8k16.row.col.f32.bf16.bf16.f32 "
                 "{%0,%1,%2,%3}, {%4,%5,%6,%7}, {%8,%9}, {%0,%1,%2,%3};"
                 : "+f"(d[0]), "+f"(d[1]), "+f"(d[2]), "+f"(d[3])
                 : "r"(a[0]), "r"(a[1]), "r"(a[2]), "r"(a[3]), "r"(b[0]), "r"(b[1]));
}
__device__ __forceinline__ void split_bf16(float v, __nv_bfloat16& h, __nv_bfloat16& l) {
    h = __float2bfloat16(v);
    l = __float2bfloat16(v - __bfloat162float(h));
}
__device__ __forceinline__ uint32_t pack_pair(float a, float b) {
    __nv_bfloat162 p = __halves2bfloat162(__float2bfloat16(a), __float2bfloat16(b));
    return *(uint32_t*)&p;
}

static constexpr int PITCHB = 80;               // 32 bf16 k-chunk rows, pitch 40 bf16
static constexpr int TILEB = 128 * PITCHB;      // 10240
static constexpr int SA_H = 0, SA_L = 10240, SB_H = 20480, SB_L = 30720;
static constexpr int BUFB = 40960;
static constexpr int K1_SMEM = 2 * BUFB;        // fp32 stage reuses buffers post-loop

// k3: V 128x32 hi/lo + P 64x32 hi/lo per buffer, 3-stage ring (R9 winner)
static constexpr int PTILEB = 64 * PITCHB;                  // 5120
static constexpr int K3_SBH = 2 * TILEB;                    // 20480
static constexpr int K3_SBL = K3_SBH + PTILEB;              // 25600
static constexpr int K3_BUF = K3_SBL + PTILEB;              // 30720
static constexpr int K3_SMEM = 3 * K3_BUF;                  // 92160

// ---------------------------------------------------------------------------
// K0: split/transpose x -> xT_hi/lo [b][n][c]
// ---------------------------------------------------------------------------
__global__ void k0_split(const float* __restrict__ x) {
    __shared__ float t[32][33];
    const int b = blockIdx.z, c0 = blockIdx.x * 32, n0 = blockIdx.y * 32;
    const int tx = threadIdx.x, ty = threadIdx.y;   // 32 x 8
    const float* xb = x + (size_t)b * C_ * N_;
    #pragma unroll
    for (int r = 0; r < 4; r++) {
        int c = ty + r * 8;
        t[c][tx] = xb[(size_t)(c0 + c) * N_ + n0 + tx];
    }
    __syncthreads();
    __nv_bfloat16* Th = g_xT_hi + (size_t)b * N_ * C_;
    __nv_bfloat16* Tl = g_xT_lo + (size_t)b * N_ * C_;
    #pragma unroll
    for (int r = 0; r < 4; r++) {
        int n = ty + r * 8;
        float v = t[tx][n];
        __nv_bfloat16 h, l;
        split_bf16(v, h, l);
        size_t o = (size_t)(n0 + n) * C_ + c0 + tx;
        Th[o] = h; Tl[o] = l;
    }
}

// ---------------------------------------------------------------------------
// K1: P-tile = exp(mask(xT * xT^T)), symmetry tj>=ti (early exit grid),
// cp.async double buffer. grid (25, 25, B), 256 threads (8 warps 2m x 4n).
// ---------------------------------------------------------------------------
__device__ __forceinline__ void k1_mma_chunk(float acc[4][4][4], uint32_t base,
                                             int a_off, int b_off0, int b_off1) {
    #pragma unroll
    for (int ks = 0; ks < 2; ks++) {
        const int kb = ks * 32;
        uint32_t ah[4][4], al[4][4], bh[2][4], bl[2][4];
        #pragma unroll
        for (int ma = 0; ma < 4; ma++)
            ldm_x4(ah[ma], base + SA_H + a_off + ma * 16 * PITCHB + kb);
        ldm_x4(bh[0], base + SB_H + b_off0 + kb);
        ldm_x4(bh[1], base + SB_H + b_off1 + kb);
        #pragma unroll
        for (int ma = 0; ma < 4; ma++)
            #pragma unroll
            for (int na = 0; na < 4; na++)
                mma_bf16(acc[ma][na], ah[ma], &bh[na >> 1][(na & 1) * 2]);
        ldm_x4(bl[0], base + SB_L + b_off0 + kb);
        ldm_x4(bl[1], base + SB_L + b_off1 + kb);
        #pragma unroll
        for (int ma = 0; ma < 4; ma++)
            #pragma unroll
            for (int na = 0; na < 4; na++)
                mma_bf16(acc[ma][na], ah[ma], &bl[na >> 1][(na & 1) * 2]);
        #pragma unroll
        for (int ma = 0; ma < 4; ma++)
            ldm_x4(al[ma], base + SA_L + a_off + ma * 16 * PITCHB + kb);
        #pragma unroll
        for (int ma = 0; ma < 4; ma++)
            #pragma unroll
            for (int na = 0; na < 4; na++)
                mma_bf16(acc[ma][na], al[ma], &bh[na >> 1][(na & 1) * 2]);
    }
}

__device__ __forceinline__ void k1_issue(uint32_t sbuf, int tid, int c0, int i0, int j0,
                                         const __nv_bfloat16* Xh, const __nv_bfloat16* Xl) {
    #pragma unroll
    for (int q = 0; q < 8; q++) {
        int e = tid + q * 256;
        int tile = e >> 9, row = (e >> 2) & 127, p = e & 3;
        int gr = min(((tile < 2) ? i0 : j0) + row, N_ - 1);
        const __nv_bfloat16* src = ((tile & 1) ? Xl : Xh) + (size_t)gr * C_ + c0;
        uint32_t dst = sbuf + tile * TILEB + row * PITCHB + p * 16;
        asm volatile("cp.async.cg.shared.global [%0], [%1], 16;"
                     :: "r"(dst), "l"((const char*)src + p * 16) : "memory");
    }
    asm volatile("cp.async.commit_group;" ::: "memory");
}

__global__ void __launch_bounds__(256, 2) k1_gram() {
    extern __shared__ char smem[];
    const uint32_t sb = smem_u32(smem);
    const int tid = threadIdx.x, wid = tid >> 5, lane = tid & 31;
    const int g = lane >> 2, t4 = lane & 3;
    const int ti = blockIdx.x, tj = blockIdx.y, b = blockIdx.z;
    if (tj < ti) return;
    const int i0 = ti * 128, j0 = tj * 128;
    const int wm = wid & 1, wn = wid >> 1;

    const int ab = lane >> 3;
    const int a_row = (ab & 1) * 8 + (lane & 7);
    const int a_colb = ((ab >> 1) * 8) * 2;
    const int a_off = (wm * 64 + a_row) * PITCHB + a_colb;
    const int b_row4 = lane & 7;
    const int b_k8 = ((lane >> 3) & 1) * 16;
    const int b_nsel = lane >> 4;
    const int b_off0 = (wn * 32 + (0 * 2 + b_nsel) * 8 + b_row4) * PITCHB + b_k8;
    const int b_off1 = (wn * 32 + (1 * 2 + b_nsel) * 8 + b_row4) * PITCHB + b_k8;

    const __nv_bfloat16* Xh = g_xT_hi + (size_t)b * N_ * C_;
    const __nv_bfloat16* Xl = g_xT_lo + (size_t)b * N_ * C_;

    float acc[4][4][4];
    #pragma unroll
    for (int i = 0; i < 4; i++)
        #pragma unroll
        for (int j = 0; j < 4; j++)
            #pragma unroll
            for (int q = 0; q < 4; q++) acc[i][j][q] = 0.0f;

    k1_issue(sb, tid, 0, i0, j0, Xh, Xl);
    #pragma unroll
    for (int kc = 0; kc < 4; kc++) {
        if (kc < 3) {
            k1_issue(sb + ((kc + 1) & 1) * BUFB, tid, (kc + 1) * 32, i0, j0, Xh, Xl);
            asm volatile("cp.async.wait_group 1;" ::: "memory");
        } else {
            asm volatile("cp.async.wait_group 0;" ::: "memory");
        }
        __syncthreads();
        k1_mma_chunk(acc, sb + (kc & 1) * BUFB, a_off, b_off0, b_off1);
        __syncthreads();
    }

    // stage exp(masked E) fp32, pitch 133 (reuses buffer smem)
    float* stg = (float*)smem;
    const bool diagblk = (ti == tj);
    #pragma unroll
    for (int ma = 0; ma < 4; ma++)
        #pragma unroll
        for (int na = 0; na < 4; na++) {
            int r0 = wm * 64 + ma * 16 + g;
            int cc = wn * 32 + na * 8 + t4 * 2;
            float d0 = acc[ma][na][0], d1 = acc[ma][na][1];
            float d2 = acc[ma][na][2], d3 = acc[ma][na][3];
            if (diagblk) {
                if (r0 == cc) d0 = 0.0f;
                if (r0 == cc + 1) d1 = 0.0f;
                if (r0 + 8 == cc) d2 = 0.0f;
                if (r0 + 8 == cc + 1) d3 = 0.0f;
            }
            stg[r0 * 133 + cc] = __expf(d0);
            stg[r0 * 133 + cc + 1] = __expf(d1);
            stg[(r0 + 8) * 133 + cc] = __expf(d2);
            stg[(r0 + 8) * 133 + cc + 1] = __expf(d3);
        }
    __syncthreads();

    const int ilim = min(128, N_ - i0), jlim = min(128, N_ - j0);

    if (tid < 128) {                      // row sums, split chains
        int row = tid;
        if (row < ilim) {
            float s0 = 0.0f, s1 = 0.0f, s2 = 0.0f, s3 = 0.0f;
            const float* r = stg + row * 133;
            int c = 0;
            for (; c + 3 < jlim; c += 4) {
                s0 += r[c]; s1 += r[c + 1]; s2 += r[c + 2]; s3 += r[c + 3];
            }
            for (; c < jlim; c++) s0 += r[c];
            g_psum[((size_t)b * NT + tj) * N_ + i0 + row] = (s0 + s1) + (s2 + s3);
        }
    } else if (ti != tj) {                // col sums (mirror), split chains
        int jr = tid - 128;
        if (jr < jlim) {
            float s0 = 0.0f, s1 = 0.0f, s2 = 0.0f, s3 = 0.0f;
            const float* cptr = stg + jr;
            int ic = 0;
            for (; ic + 3 < ilim; ic += 4) {
                s0 += cptr[ic * 133];
                s1 += cptr[(ic + 1) * 133];
                s2 += cptr[(ic + 2) * 133];
                s3 += cptr[(ic + 3) * 133];
            }
            for (; ic < ilim; ic++) s0 += cptr[ic * 133];
            g_psum[((size_t)b * NT + ti) * N_ + j0 + jr] = (s0 + s1) + (s2 + s3);
        }
    }

    // coalesced staged P stores, widened to 8B (uint2) per array
    __nv_bfloat16* PhB = g_P_hi + (size_t)b * NN;
    __nv_bfloat16* PlB = g_P_lo + (size_t)b * NN;
    for (int e = tid; e < 4096; e += 256) {
        int r = e >> 5, q4 = e & 31;       // row 0..127, 4-col group 0..31
        int col = q4 * 4;
        if (r < ilim && col < jlim) {
            const float* s = stg + r * 133 + col;
            uint2 vh, vl;
            {
                __nv_bfloat16 h0, l0, h1, l1, h2, l2, h3, l3;
                split_bf16(s[0], h0, l0);
                split_bf16(s[1], h1, l1);
                split_bf16(s[2], h2, l2);
                split_bf16(s[3], h3, l3);
                __nv_bfloat162 ph0 = __halves2bfloat162(h0, h1);
                __nv_bfloat162 ph1 = __halves2bfloat162(h2, h3);
                __nv_bfloat162 pl0 = __halves2bfloat162(l0, l1);
                __nv_bfloat162 pl1 = __halves2bfloat162(l2, l3);
                vh = make_uint2(*(uint32_t*)&ph0, *(uint32_t*)&ph1);
                vl = make_uint2(*(uint32_t*)&pl0, *(uint32_t*)&pl1);
            }
            size_t off = (size_t)(i0 + r) * N_ + j0 + col;
            *(uint2*)(PhB + off) = vh;
            *(uint2*)(PlB + off) = vl;
        }
    }
    if (ti != tj) {
        for (int e = tid; e < 4096; e += 256) {
            int jr = e >> 5, q4 = e & 31;
            int ic = q4 * 4;
            if (jr < jlim && ic < ilim) {
                float a0 = stg[(ic + 0) * 133 + jr];
                float a1 = stg[(ic + 1) * 133 + jr];
                float a2 = stg[(ic + 2) * 133 + jr];
                float a3 = stg[(ic + 3) * 133 + jr];
                uint2 vh, vl;
                {
                    __nv_bfloat16 h0, l0, h1, l1, h2, l2, h3, l3;
                    split_bf16(a0, h0, l0);
                    split_bf16(a1, h1, l1);
                    split_bf16(a2, h2, l2);
                    split_bf16(a3, h3, l3);
                    __nv_bfloat162 ph0 = __halves2bfloat162(h0, h1);
                    __nv_bfloat162 ph1 = __halves2bfloat162(h2, h3);
                    __nv_bfloat162 pl0 = __halves2bfloat162(l0, l1);
                    __nv_bfloat162 pl1 = __halves2bfloat162(l2, l3);
                    vh = make_uint2(*(uint32_t*)&ph0, *(uint32_t*)&ph1);
                    vl = make_uint2(*(uint32_t*)&pl0, *(uint32_t*)&pl1);
                }
                size_t off = (size_t)(j0 + jr) * N_ + i0 + ic;
                *(uint2*)(PhB + off) = vh;
                *(uint2*)(PlB + off) = vl;
            }
        }
    }
}

// ---------------------------------------------------------------------------
// K2b: per-block inv for a 32-i slice, then Vs split. grid (98, B), 256 thr.
// ---------------------------------------------------------------------------
__global__ void __launch_bounds__(256) k2b_vscale(const float* __restrict__ x,
                                                  const float* __restrict__ gamma_p,
                                                  float* __restrict__ g_sec) {
    const int b = blockIdx.y, i0 = blockIdx.x * 32;
    const int tid = threadIdx.x;
    __shared__ float sinv[32];
    if (tid < 32) {
        const float* p = g_psum + (size_t)b * NT * N_ + i0 + tid;
        float s = 0.0f;
        #pragma unroll
        for (int t = 0; t < NT; t++) s += p[(size_t)t * N_];
        sinv[tid] = 1.0f / s;
    }
    if (b == 0 && blockIdx.x == 0 && tid == 0) g_sec[0] = gamma_p[0];
    __syncthreads();

    const int c = tid >> 1, ih = (tid & 1) * 16;
    const float* src = x + ((size_t)b * C_ + c) * N_ + i0 + ih;
    const size_t dsto = ((size_t)b * C_ + c) * N_ + i0 + ih;
    #pragma unroll
    for (int q = 0; q < 16; q += 2) {
        float2 f = *(const float2*)(src + q);
        float a0 = f.x * sinv[ih + q];
        float a1 = f.y * sinv[ih + q + 1];
        __nv_bfloat16 h0, l0, h1, l1;
        split_bf16(a0, h0, l0);
        split_bf16(a1, h1, l1);
        *(__nv_bfloat162*)(g_V_hi + dsto + q) = __halves2bfloat162(h0, h1);
        *(__nv_bfloat162*)(g_V_lo + dsto + q) = __halves2bfloat162(l0, l1);
    }
}

// ---------------------------------------------------------------------------
// K3 (R9 winner): out[c,j] = sum_i Vs[c,i] * P[j,i]. Tile 128c x 64j, grid
// 392, 3-stage cp.async ring, 1 sync/chunk, 4m x 2n warps. Fused epilogue.
// ---------------------------------------------------------------------------
__device__ __forceinline__ void k3_issue(uint32_t sbuf, int tid, int iC, int j0,
                                         const __nv_bfloat16* Vh, const __nv_bfloat16* Vl,
                                         const __nv_bfloat16* Ph, const __nv_bfloat16* Pl) {
    #pragma unroll
    for (int q = 0; q < 6; q++) {
        int e = tid + q * 256;             // e in [0, 1536)
        int p = e & 3;
        uint32_t dst;
        const __nv_bfloat16* src;
        if (e < 1024) {                    // V tiles: 128 rows
            int row = (e >> 2) & 127;
            int hl = e >> 9;
            dst = sbuf + hl * TILEB + row * PITCHB + p * 16;
            src = (hl ? Vl : Vh) + (size_t)row * N_ + iC;
        } else {                           // P tiles: 64 rows
            int e2 = e - 1024;
            int row = (e2 >> 2) & 63;
            int hl = e2 >> 8;
            dst = sbuf + (hl ? K3_SBL : K3_SBH) + row * PITCHB + p * 16;
            src = (hl ? Pl : Ph) + (size_t)(j0 + row) * N_ + iC;
        }
        asm volatile("cp.async.cg.shared.global [%0], [%1], 16;"
                     :: "r"(dst), "l"((const char*)src + p * 16) : "memory");
    }
    asm volatile("cp.async.commit_group;" ::: "memory");
}

__device__ __forceinline__ void k3_mma_chunk(float acc[2][4][4], uint32_t base,
                                             int a_off, int b_off0, int b_off1) {
    #pragma unroll
    for (int ks = 0; ks < 2; ks++) {
        const int kb = ks * 32;
        uint32_t ah[2][4], al[2][4], bh[2][4], bl[2][4];
        #pragma unroll
        for (int ma = 0; ma < 2; ma++)
            ldm_x4(ah[ma], base + SA_H + a_off + ma * 16 * PITCHB + kb);
        ldm_x4(bh[0], base + K3_SBH + b_off0 + kb);
        ldm_x4(bh[1], base + K3_SBH + b_off1 + kb);
        #pragma unroll
        for (int ma = 0; ma < 2; ma++)
            #pragma unroll
            for (int na = 0; na < 4; na++)
                mma_bf16(acc[ma][na], ah[ma], &bh[na >> 1][(na & 1) * 2]);
        ldm_x4(bl[0], base + K3_SBL + b_off0 + kb);
        ldm_x4(bl[1], base + K3_SBL + b_off1 + kb);
        #pragma unroll
        for (int ma = 0; ma < 2; ma++)
            #pragma unroll
            for (int na = 0; na < 4; na++)
                mma_bf16(acc[ma][na], ah[ma], &bl[na >> 1][(na & 1) * 2]);
        #pragma unroll
        for (int ma = 0; ma < 2; ma++)
            ldm_x4(al[ma], base + SA_L + a_off + ma * 16 * PITCHB + kb);
        #pragma unroll
        for (int ma = 0; ma < 2; ma++)
            #pragma unroll
            for (int na = 0; na < 4; na++)
                mma_bf16(acc[ma][na], al[ma], &bh[na >> 1][(na & 1) * 2]);
    }
}

__global__ void __launch_bounds__(256, 2) k3_out(const float* __restrict__ x,
                                                 const float* __restrict__ gamma_p,
                                                 float* __restrict__ y_out,
                                                 float* __restrict__ o_out,
                                                 float* __restrict__ x_out) {
    extern __shared__ char smem[];
    const uint32_t sb = smem_u32(smem);
    const int tid = threadIdx.x, wid = tid >> 5, lane = tid & 31;
    const int g = lane >> 2, t4 = lane & 3;
    const int b = blockIdx.x % B_, j0 = (blockIdx.x / B_) * 64;
    const int wm = wid & 3, wn = wid >> 2;      // 4m x 2n

    const int ab = lane >> 3;
    const int a_row = (ab & 1) * 8 + (lane & 7);
    const int a_colb = ((ab >> 1) * 8) * 2;
    const int a_off = (wm * 32 + a_row) * PITCHB + a_colb;
    const int b_row4 = lane & 7;
    const int b_k8 = ((lane >> 3) & 1) * 16;
    const int b_nsel = lane >> 4;
    const int b_off0 = (wn * 32 + (0 * 2 + b_nsel) * 8 + b_row4) * PITCHB + b_k8;
    const int b_off1 = (wn * 32 + (1 * 2 + b_nsel) * 8 + b_row4) * PITCHB + b_k8;

    const __nv_bfloat16* Vh = g_V_hi + (size_t)b * C_ * N_;
    const __nv_bfloat16* Vl = g_V_lo + (size_t)b * C_ * N_;
    const __nv_bfloat16* Ph = g_P_hi + (size_t)b * NN;
    const __nv_bfloat16* Pl = g_P_lo + (size_t)b * NN;
    const float* xb = x + (size_t)b * C_ * N_;

    float acc[2][4][4];
    #pragma unroll
    for (int i = 0; i < 2; i++)
        #pragma unroll
        for (int j = 0; j < 4; j++)
            #pragma unroll
            for (int q = 0; q < 4; q++) acc[i][j][q] = 0.0f;

    k3_issue(sb, tid, 0, j0, Vh, Vl, Ph, Pl);

    int buf = 0;
    for (int kc = 0; kc < 98; kc++) {
        if (kc < 97) {
            int nbuf = (buf == 2) ? 0 : buf + 1;
            k3_issue(sb + nbuf * K3_BUF, tid, (kc + 1) * 32, j0, Vh, Vl, Ph, Pl);
            asm volatile("cp.async.wait_group 1;" ::: "memory");
        } else {
            asm volatile("cp.async.wait_group 0;" ::: "memory");
        }
        __syncthreads();
        k3_mma_chunk(acc, sb + buf * K3_BUF, a_off, b_off0, b_off1);
        buf = (buf == 2) ? 0 : buf + 1;
    }

    const float gamma = *gamma_p;
    #pragma unroll
    for (int ma = 0; ma < 2; ma++)
        #pragma unroll
        for (int na = 0; na < 4; na++) {
            int c = wm * 32 + ma * 16 + g;
            int j = j0 + wn * 32 + na * 8 + t4 * 2;
            size_t idx0 = ((size_t)b * C_ + c) * N_ + j;
            size_t idx1 = ((size_t)b * C_ + c + 8) * N_ + j;
            float o0 = fmaxf(acc[ma][na][0], 0.0f);
            float o1 = fmaxf(acc[ma][na][1], 0.0f);
            float o2 = fmaxf(acc[ma][na][2], 0.0f);
            float o3 = fmaxf(acc[ma][na][3], 0.0f);
            float2 xi0 = *(const float2*)&xb[(size_t)c * N_ + j];
            float2 xi1 = *(const float2*)&xb[(size_t)(c + 8) * N_ + j];
            *(float2*)&o_out[idx0] = make_float2(o0, o1);
            *(float2*)&o_out[idx1] = make_float2(o2, o3);
            *(float2*)&y_out[idx0] = make_float2(gamma * o0 + xi0.x, gamma * o1 + xi0.y);
            *(float2*)&y_out[idx1] = make_float2(gamma * o2 + xi1.x, gamma * o3 + xi1.y);
            *(float2*)&x_out[idx0] = xi0;
            *(float2*)&x_out[idx1] = xi1;
        }
}

// ---------------------------------------------------------------------------
extern "C" void kernel_launch(void* const* d_in, const int* in_sizes, int n_in,
                              void* d_out, int out_size) {
    const float* x     = (const float*)d_in[0];
    const float* gamma = (const float*)d_in[1];
    float* out = (float*)d_out;

    float* y_sec = out;
    float* o_sec = out + XE;
    float* x_sec = out + 2 * XE;
    float* g_sec = out + 3 * XE;

    cudaFuncSetAttribute(k1_gram, cudaFuncAttributeMaxDynamicSharedMemorySize, K1_SMEM);
    cudaFuncSetAttribute(k3_out, cudaFuncAttributeMaxDynamicSharedMemorySize, K3_SMEM);

    k0_split<<<dim3(4, 98, B_), dim3(32, 8)>>>(x);
    k1_gram<<<dim3(NT, NT, B_), 256, K1_SMEM>>>();
    k2b_vscale<<<dim3(98, B_), 256>>>(x, gamma, g_sec);
    k3_out<<<dim3(49 * B_), 256, K3_SMEM>>>(x, gamma, y_sec, o_sec, x_sec);
}